// round 1
// baseline (speedup 1.0000x reference)
#include <cuda_runtime.h>
#include <cstdint>

#define T_DIM   8192
#define C_DIM   8
#define CAP     1024
#define NT      512
#define NWARPS  (NT / 32)
#define RANK0   7371          // floor(0.9 * (T_DIM-1)), 0-indexed lower order stat
#define A_LO    1.15f         // window bracketing the 0.9 quantile of N(0,1)
#define B_HI    1.45f

// fraction for linear interpolation: 0.9*(T-1) - RANK0
__device__ __constant__ float kFrac = (float)(0.9 * (double)(T_DIM - 1) - (double)RANK0);

// monotonic float -> uint key mapping (total order, handles negatives)
__device__ __forceinline__ uint32_t fkey(float v) {
    uint32_t u = __float_as_uint(v);
    return (u & 0x80000000u) ? ~u : (u | 0x80000000u);
}
__device__ __forceinline__ float fkey_inv(uint32_t k) {
    uint32_t u = (k & 0x80000000u) ? (k ^ 0x80000000u) : ~k;
    return __uint_as_float(u);
}

// Exact rank-r (0-indexed, ascending) selection over n candidates in smem,
// one warp, 4-pass byte radix with a per-warp 256-bin smem histogram.
__device__ float warp_select(const float* cand, uint32_t* hist, int n, int r) {
    const int lane = threadIdx.x & 31;
    uint32_t prefix = 0, done = 0;
    for (int shift = 24; shift >= 0; shift -= 8) {
        for (int i = lane; i < 256; i += 32) hist[i] = 0;
        __syncwarp();
        for (int i = lane; i < n; i += 32) {
            uint32_t k = fkey(cand[i]);
            if ((k & done) == prefix) atomicAdd(&hist[(k >> shift) & 255u], 1u);
        }
        __syncwarp();
        uint32_t bv[8];
        uint32_t loc = 0;
#pragma unroll
        for (int j = 0; j < 8; j++) { bv[j] = hist[lane * 8 + j]; loc += bv[j]; }
        // inclusive warp scan of per-lane bin sums
        uint32_t pre = loc;
#pragma unroll
        for (int d = 1; d < 32; d <<= 1) {
            uint32_t t = __shfl_up_sync(0xffffffffu, pre, d);
            if (lane >= d) pre += t;
        }
        int excl = (int)(pre - loc);
        bool myfind = (r >= excl) && (r < excl + (int)loc);
        uint32_t ball = __ballot_sync(0xffffffffu, myfind);
        int src = __ffs(ball) - 1;
        int bin_out = 0, rem_out = 0;
        if (myfind) {
            int rem = r - excl;
            int bsel = 0;
            bool found = false;
#pragma unroll
            for (int j = 0; j < 8; j++) {
                if (!found) {
                    if (rem < (int)bv[j]) { bsel = j; found = true; }
                    else rem -= (int)bv[j];
                }
            }
            bin_out = lane * 8 + bsel;
            rem_out = rem;
        }
        int bin = __shfl_sync(0xffffffffu, bin_out, src);
        r       = __shfl_sync(0xffffffffu, rem_out, src);
        prefix |= (uint32_t)bin << shift;
        done   |= 0xFFu << shift;
        __syncwarp();
    }
    return fkey_inv(prefix);
}

// Block-wide exact rank-r selection straight from global memory (fallback path,
// statistically never taken; data is L2-hot from the main pass).
__device__ float block_select_global(const float* __restrict__ x, int b, int c, int r,
                                     uint32_t* hist, int* bcast) {
    const int tid = threadIdx.x;
    uint32_t prefix = 0, done = 0;
    for (int shift = 24; shift >= 0; shift -= 8) {
        for (int i = tid; i < 256; i += NT) hist[i] = 0;
        __syncthreads();
        for (int t = tid; t < T_DIM; t += NT) {
            float v = x[((size_t)b * T_DIM + t) * C_DIM + c];
            uint32_t k = fkey(v);
            if ((k & done) == prefix) atomicAdd(&hist[(k >> shift) & 255u], 1u);
        }
        __syncthreads();
        if (tid == 0) {
            int rr = r, bin = 255;
            for (int j = 0; j < 256; j++) {
                if (rr < (int)hist[j]) { bin = j; break; }
                rr -= (int)hist[j];
            }
            bcast[0] = bin; bcast[1] = rr;
        }
        __syncthreads();
        prefix |= (uint32_t)bcast[0] << shift;
        r = bcast[1];
        done |= 0xFFu << shift;
        __syncthreads();
    }
    return fkey_inv(prefix);
}

__global__ void __launch_bounds__(NT, 3) stat_kernel(
    const float* __restrict__ x, const float* __restrict__ W,
    const float* __restrict__ bias, float* __restrict__ out)
{
    __shared__ float    s_cand[C_DIM][CAP];      // 32 KB candidate lists
    __shared__ int      s_cnt[C_DIM];            // true window counts
    __shared__ float    s_wpart[NWARPS][C_DIM][3]; // per-warp partials: sum, sumsq, cntpos
    __shared__ int      s_wbelow[NWARPS][C_DIM];
    __shared__ uint32_t s_hist[C_DIM][256];      // per-warp radix histograms
    __shared__ float    s_stat[C_DIM][4];        // q, mean, cnt, std
    __shared__ int      s_below[C_DIM];
    __shared__ int      s_fb[C_DIM];
    __shared__ uint32_t s_bhist[256];
    __shared__ int      s_bcast[2];

    const int tid  = threadIdx.x;
    const int lane = tid & 31;
    const int wid  = tid >> 5;
    const int b    = blockIdx.x;

    if (tid < C_DIM) { s_cnt[tid] = 0; s_fb[tid] = 0; }
    __syncthreads();

    // ---- Main streaming pass: coalesced float4 loads, fused stats + window capture ----
    const float4* xb = reinterpret_cast<const float4*>(x + (size_t)b * T_DIM * C_DIM);
    float sum[4] = {0.f, 0.f, 0.f, 0.f};
    float ssq[4] = {0.f, 0.f, 0.f, 0.f};
    int   cpos[4] = {0, 0, 0, 0};
    int   cbel[4] = {0, 0, 0, 0};
    const int cbase = (tid & 1) * 4;   // even threads own ch 0-3, odd own ch 4-7 (NT even stride preserves parity)

#pragma unroll 4
    for (int i = tid; i < (T_DIM * C_DIM) / 4; i += NT) {
        float4 f = __ldcs(&xb[i]);
        float v[4] = {f.x, f.y, f.z, f.w};
#pragma unroll
        for (int j = 0; j < 4; j++) {
            float vv = v[j];
            sum[j] += vv;
            ssq[j]  = fmaf(vv, vv, ssq[j]);
            cpos[j] += (vv > 0.0f);
            bool below = (vv < A_LO);
            cbel[j] += below;
            if (!below && vv < B_HI) {
                int c = cbase + j;
                int idx = atomicAdd(&s_cnt[c], 1);
                if (idx < CAP) s_cand[c][idx] = vv;
            }
        }
    }

    // ---- parity-preserving warp reduction (masks 2..16 keep even/odd lanes separate) ----
#pragma unroll
    for (int m = 2; m < 32; m <<= 1) {
#pragma unroll
        for (int j = 0; j < 4; j++) {
            sum[j]  += __shfl_xor_sync(0xffffffffu, sum[j], m);
            ssq[j]  += __shfl_xor_sync(0xffffffffu, ssq[j], m);
            cpos[j] += __shfl_xor_sync(0xffffffffu, cpos[j], m);
            cbel[j] += __shfl_xor_sync(0xffffffffu, cbel[j], m);
        }
    }
    if (lane < 2) {
#pragma unroll
        for (int j = 0; j < 4; j++) {
            int c = lane * 4 + j;
            s_wpart[wid][c][0] = sum[j];
            s_wpart[wid][c][1] = ssq[j];
            s_wpart[wid][c][2] = (float)cpos[j];
            s_wbelow[wid][c]   = cbel[j];
        }
    }
    __syncthreads();

    // ---- deterministic block combine + mean/std/cnt ----
    if (tid < C_DIM) {
        float S = 0.f, Q = 0.f, P = 0.f; int Bl = 0;
        for (int w = 0; w < NWARPS; w++) {
            S  += s_wpart[w][tid][0];
            Q  += s_wpart[w][tid][1];
            P  += s_wpart[w][tid][2];
            Bl += s_wbelow[w][tid];
        }
        float mean = S / (float)T_DIM;
        float var  = (Q - S * S / (float)T_DIM) / (float)(T_DIM - 1);
        s_stat[tid][1] = mean;
        s_stat[tid][2] = P;
        s_stat[tid][3] = sqrtf(fmaxf(var, 0.0f));
        s_below[tid]   = Bl;
    }
    __syncthreads();

    // ---- per-channel exact quantile: warp radix select over the window candidates ----
    if (wid < C_DIM) {
        int c  = wid;
        int n  = s_cnt[c];
        int cb = s_below[c];
        int l0 = RANK0 - cb;                       // local rank of lower order stat
        bool ok = (n <= CAP) && (l0 >= 0) && (l0 + 1 < n);
        if (ok) {
            float v0 = warp_select(s_cand[c], s_hist[c], n, l0);
            float v1 = warp_select(s_cand[c], s_hist[c], n, l0 + 1);
            if (lane == 0) s_stat[c][0] = v0 + kFrac * (v1 - v0);
        } else {
            if (lane == 0) s_fb[c] = 1;
        }
    }
    __syncthreads();

    // ---- fallback (exact, block-wide, re-reads global; ~never executes) ----
    for (int c = 0; c < C_DIM; c++) {
        if (s_fb[c]) {
            float v0 = block_select_global(x, b, c, RANK0,     s_bhist, s_bcast);
            float v1 = block_select_global(x, b, c, RANK0 + 1, s_bhist, s_bcast);
            if (tid == 0) s_stat[c][0] = v0 + kFrac * (v1 - v0);
            __syncthreads();
        }
    }

    // ---- tiny linear layer: feats order [q, mean, cnt, std] per channel ----
    if (tid < C_DIM) {
        float acc = s_stat[tid][0] * __ldg(&W[tid * 4 + 0])
                  + s_stat[tid][1] * __ldg(&W[tid * 4 + 1])
                  + s_stat[tid][2] * __ldg(&W[tid * 4 + 2])
                  + s_stat[tid][3] * __ldg(&W[tid * 4 + 3]);
        acc += __shfl_xor_sync(0xffu, acc, 1);
        acc += __shfl_xor_sync(0xffu, acc, 2);
        acc += __shfl_xor_sync(0xffu, acc, 4);
        if (tid == 0) out[b] = acc + __ldg(&bias[0]);
    }
}

extern "C" void kernel_launch(void* const* d_in, const int* in_sizes, int n_in,
                              void* d_out, int out_size) {
    const float* x    = (const float*)d_in[0];
    const float* W    = (const float*)d_in[1];
    const float* bias = (const float*)d_in[2];
    float* out        = (float*)d_out;
    int B = in_sizes[0] / (T_DIM * C_DIM);
    stat_kernel<<<B, NT>>>(x, W, bias, out);
}

// round 2
// speedup vs baseline: 1.0708x; 1.0708x over previous
#include <cuda_runtime.h>
#include <cstdint>

#define T_DIM   8192
#define C_DIM   8
#define CAP     1024
#define NT      256
#define NWARPS  (NT / 32)
#define DEPTH   8                      // prefetch depth (independent float4 loads)
#define NVEC    (T_DIM * C_DIM / 4)    // 16384 float4 per batch row
#define GROUPS  (NVEC / (NT * DEPTH))  // 8 outer iterations
#define RANK0   7371                   // floor(0.9 * (T_DIM-1)), 0-indexed
#define A_LO    1.15f                  // window bracketing the 0.9 quantile of N(0,1)
#define B_HI    1.45f

__device__ __constant__ float kFrac = (float)(0.9 * (double)(T_DIM - 1) - (double)RANK0);

// monotonic float -> uint key (total order incl. negatives)
__device__ __forceinline__ uint32_t fkey(float v) {
    uint32_t u = __float_as_uint(v);
    return (u & 0x80000000u) ? ~u : (u | 0x80000000u);
}
__device__ __forceinline__ float fkey_inv(uint32_t k) {
    uint32_t u = (k & 0x80000000u) ? (k ^ 0x80000000u) : ~k;
    return __uint_as_float(u);
}

// Exact rank-r selection over n smem candidates; one warp, 4-pass byte radix.
__device__ float warp_select(const float* cand, uint32_t* hist, int n, int r) {
    const int lane = threadIdx.x & 31;
    uint32_t prefix = 0, done = 0;
    for (int shift = 24; shift >= 0; shift -= 8) {
        for (int i = lane; i < 256; i += 32) hist[i] = 0;
        __syncwarp();
        for (int i = lane; i < n; i += 32) {
            uint32_t k = fkey(cand[i]);
            if ((k & done) == prefix) atomicAdd(&hist[(k >> shift) & 255u], 1u);
        }
        __syncwarp();
        uint32_t bv[8];
        uint32_t loc = 0;
#pragma unroll
        for (int j = 0; j < 8; j++) { bv[j] = hist[lane * 8 + j]; loc += bv[j]; }
        uint32_t pre = loc;
#pragma unroll
        for (int d = 1; d < 32; d <<= 1) {
            uint32_t t = __shfl_up_sync(0xffffffffu, pre, d);
            if (lane >= d) pre += t;
        }
        int excl = (int)(pre - loc);
        bool myfind = (r >= excl) && (r < excl + (int)loc);
        uint32_t ball = __ballot_sync(0xffffffffu, myfind);
        int src = __ffs(ball) - 1;
        int bin_out = 0, rem_out = 0;
        if (myfind) {
            int rem = r - excl, bsel = 0;
            bool found = false;
#pragma unroll
            for (int j = 0; j < 8; j++) {
                if (!found) {
                    if (rem < (int)bv[j]) { bsel = j; found = true; }
                    else rem -= (int)bv[j];
                }
            }
            bin_out = lane * 8 + bsel;
            rem_out = rem;
        }
        int bin = __shfl_sync(0xffffffffu, bin_out, src);
        r       = __shfl_sync(0xffffffffu, rem_out, src);
        prefix |= (uint32_t)bin << shift;
        done   |= 0xFFu << shift;
        __syncwarp();
    }
    return fkey_inv(prefix);
}

// Block-wide exact rank-r selection from global (fallback; ~never taken).
__device__ float block_select_global(const float* __restrict__ x, int b, int c, int r,
                                     uint32_t* hist, int* bcast) {
    const int tid = threadIdx.x;
    uint32_t prefix = 0, done = 0;
    for (int shift = 24; shift >= 0; shift -= 8) {
        for (int i = tid; i < 256; i += NT) hist[i] = 0;
        __syncthreads();
        for (int t = tid; t < T_DIM; t += NT) {
            float v = x[((size_t)b * T_DIM + t) * C_DIM + c];
            uint32_t k = fkey(v);
            if ((k & done) == prefix) atomicAdd(&hist[(k >> shift) & 255u], 1u);
        }
        __syncthreads();
        if (tid == 0) {
            int rr = r, bin = 255;
            for (int j = 0; j < 256; j++) {
                if (rr < (int)hist[j]) { bin = j; break; }
                rr -= (int)hist[j];
            }
            bcast[0] = bin; bcast[1] = rr;
        }
        __syncthreads();
        prefix |= (uint32_t)bcast[0] << shift;
        r = bcast[1];
        done |= 0xFFu << shift;
        __syncthreads();
    }
    return fkey_inv(prefix);
}

__global__ void __launch_bounds__(NT, 4) stat_kernel(
    const float* __restrict__ x, const float* __restrict__ W,
    const float* __restrict__ bias, float* __restrict__ out)
{
    __shared__ float    s_cand[C_DIM][CAP];        // 32 KB candidate lists
    __shared__ int      s_cnt[C_DIM];
    __shared__ float    s_wpart[NWARPS][C_DIM][3]; // per-warp sum/sumsq/cntpos
    __shared__ int      s_wbelow[NWARPS][C_DIM];
    __shared__ uint32_t s_hist[C_DIM][256];        // per-warp radix histograms
    __shared__ float    s_stat[C_DIM][4];          // q, mean, cnt, std
    __shared__ int      s_below[C_DIM];
    __shared__ int      s_fb[C_DIM];
    __shared__ uint32_t s_bhist[256];
    __shared__ int      s_bcast[2];

    const int tid  = threadIdx.x;
    const int lane = tid & 31;
    const int wid  = tid >> 5;
    const int b    = blockIdx.x;

    if (tid < C_DIM) { s_cnt[tid] = 0; s_fb[tid] = 0; }
    __syncthreads();

    // ---- Main streaming pass: 8-deep batched float4 loads (MLP=8), fused stats ----
    const float4* xb = reinterpret_cast<const float4*>(x + (size_t)b * T_DIM * C_DIM);
    float sum[4] = {0.f, 0.f, 0.f, 0.f};
    float ssq[4] = {0.f, 0.f, 0.f, 0.f};
    int   cpos[4] = {0, 0, 0, 0};
    int   cbel[4] = {0, 0, 0, 0};
    const int cbase = (tid & 1) * 4;   // even threads own ch 0-3, odd own ch 4-7

#pragma unroll 1
    for (int g = 0; g < GROUPS; g++) {
        float4 buf[DEPTH];
        const int base = g * DEPTH * NT + tid;
#pragma unroll
        for (int k = 0; k < DEPTH; k++)
            buf[k] = __ldcs(&xb[base + k * NT]);     // independent, front-batched

#pragma unroll
        for (int k = 0; k < DEPTH; k++) {
            float v[4] = {buf[k].x, buf[k].y, buf[k].z, buf[k].w};
            int hit = 0;
#pragma unroll
            for (int j = 0; j < 4; j++) {
                float vv = v[j];
                sum[j] += vv;
                ssq[j]  = fmaf(vv, vv, ssq[j]);
                cpos[j] += (vv > 0.0f);
                bool below = (vv < A_LO);
                cbel[j] += below;
                hit |= (int)(!below && (vv < B_HI)) << j;
            }
            if (hit) {                                // rare (~19% per float4)
#pragma unroll
                for (int j = 0; j < 4; j++) {
                    if (hit & (1 << j)) {
                        int c = cbase + j;
                        int idx = atomicAdd(&s_cnt[c], 1);
                        if (idx < CAP) s_cand[c][idx] = v[j];
                    }
                }
            }
        }
    }

    // ---- parity-preserving warp reduction (masks 2..16 keep even/odd separate) ----
#pragma unroll
    for (int m = 2; m < 32; m <<= 1) {
#pragma unroll
        for (int j = 0; j < 4; j++) {
            sum[j]  += __shfl_xor_sync(0xffffffffu, sum[j], m);
            ssq[j]  += __shfl_xor_sync(0xffffffffu, ssq[j], m);
            cpos[j] += __shfl_xor_sync(0xffffffffu, cpos[j], m);
            cbel[j] += __shfl_xor_sync(0xffffffffu, cbel[j], m);
        }
    }
    if (lane < 2) {
#pragma unroll
        for (int j = 0; j < 4; j++) {
            int c = lane * 4 + j;
            s_wpart[wid][c][0] = sum[j];
            s_wpart[wid][c][1] = ssq[j];
            s_wpart[wid][c][2] = (float)cpos[j];
            s_wbelow[wid][c]   = cbel[j];
        }
    }
    __syncthreads();

    // ---- deterministic block combine ----
    if (tid < C_DIM) {
        float S = 0.f, Q = 0.f, P = 0.f; int Bl = 0;
        for (int w = 0; w < NWARPS; w++) {
            S  += s_wpart[w][tid][0];
            Q  += s_wpart[w][tid][1];
            P  += s_wpart[w][tid][2];
            Bl += s_wbelow[w][tid];
        }
        float mean = S / (float)T_DIM;
        float var  = (Q - S * S / (float)T_DIM) / (float)(T_DIM - 1);
        s_stat[tid][1] = mean;
        s_stat[tid][2] = P;
        s_stat[tid][3] = sqrtf(fmaxf(var, 0.0f));
        s_below[tid]   = Bl;
    }
    __syncthreads();

    // ---- per-channel exact quantile: one warp per channel, radix select ----
    if (wid < C_DIM) {
        int c  = wid;
        int n  = s_cnt[c];
        int cb = s_below[c];
        int l0 = RANK0 - cb;
        bool ok = (n <= CAP) && (l0 >= 0) && (l0 + 1 < n);
        if (ok) {
            float v0 = warp_select(s_cand[c], s_hist[c], n, l0);
            float v1 = warp_select(s_cand[c], s_hist[c], n, l0 + 1);
            if (lane == 0) s_stat[c][0] = v0 + kFrac * (v1 - v0);
        } else {
            if (lane == 0) s_fb[c] = 1;
        }
    }
    __syncthreads();

    // ---- exact fallback (block-wide, re-reads global; statistically never) ----
    for (int c = 0; c < C_DIM; c++) {
        if (s_fb[c]) {
            float v0 = block_select_global(x, b, c, RANK0,     s_bhist, s_bcast);
            float v1 = block_select_global(x, b, c, RANK0 + 1, s_bhist, s_bcast);
            if (tid == 0) s_stat[c][0] = v0 + kFrac * (v1 - v0);
            __syncthreads();
        }
    }

    // ---- tiny linear layer: feats order [q, mean, cnt, std] per channel ----
    if (tid < C_DIM) {
        float acc = s_stat[tid][0] * __ldg(&W[tid * 4 + 0])
                  + s_stat[tid][1] * __ldg(&W[tid * 4 + 1])
                  + s_stat[tid][2] * __ldg(&W[tid * 4 + 2])
                  + s_stat[tid][3] * __ldg(&W[tid * 4 + 3]);
        acc += __shfl_xor_sync(0xffu, acc, 1);
        acc += __shfl_xor_sync(0xffu, acc, 2);
        acc += __shfl_xor_sync(0xffu, acc, 4);
        if (tid == 0) out[b] = acc + __ldg(&bias[0]);
    }
}

extern "C" void kernel_launch(void* const* d_in, const int* in_sizes, int n_in,
                              void* d_out, int out_size) {
    const float* x    = (const float*)d_in[0];
    const float* W    = (const float*)d_in[1];
    const float* bias = (const float*)d_in[2];
    float* out        = (float*)d_out;
    int B = in_sizes[0] / (T_DIM * C_DIM);
    stat_kernel<<<B, NT>>>(x, W, bias, out);
}